// round 16
// baseline (speedup 1.0000x reference)
#include <cuda_runtime.h>
#include <cuda_fp16.h>
#include <cstdint>
#include <cstddef>

#define N_CLASS 8192
#define FEAT    1024
#define BATCH   1024

#define TM 128
#define TN 128
#define TK 64
#define KTILES (FEAT / TK)        // 16
#define A_BYTES (TM * 128)        // 16 KB (128 rows x 128B)
#define B_BYTES (TN * 128)        // 16 KB
#define STAGE_BYTES (A_BYTES + B_BYTES)   // 32 KB
#define CTRL_OFF (2 * STAGE_BYTES)        // 64 KB
#define SMEM_TOTAL (CTRL_OFF + 128)

#define NTILE (N_CLASS / TM)                  // 64
#define NTRI  (NTILE * (NTILE + 1) / 2)       // 2080 upper-triangle tiles
#define NSM   152
#define WAVE1 (NSM * 3)                       // 456 = exactly one wave @3 CTAs/SM
#define ROWS_PER_CTA 18                       // 456*18 = 8208 >= 8192
#define CAP 32

// ---------------- device scratch (no allocations allowed) ----------------
__device__ __half g_protos[(size_t)N_CLASS * FEAT];  // 16 MB fp16 protos
__device__ float  g_rowsum[N_CLASS];
__device__ int    g_done;
__device__ int    g_ready;

// ---------------- helpers ----------------
__device__ __forceinline__ uint32_t smem_u32(const void* p) {
    uint32_t a;
    asm("{ .reg .u64 t; cvta.to.shared.u64 t, %1; cvt.u32.u64 %0, t; }" : "=r"(a) : "l"(p));
    return a;
}
__device__ __forceinline__ void ldmatrix_x4(uint32_t& r0, uint32_t& r1,
                                            uint32_t& r2, uint32_t& r3, uint32_t addr) {
    asm volatile("ldmatrix.sync.aligned.m8n8.x4.shared.b16 {%0,%1,%2,%3}, [%4];"
                 : "=r"(r0), "=r"(r1), "=r"(r2), "=r"(r3) : "r"(addr));
}
__device__ __forceinline__ void mma_f16acc(uint32_t& c0, uint32_t& c1,
                                           uint32_t a0, uint32_t a1, uint32_t a2, uint32_t a3,
                                           uint32_t b0, uint32_t b1) {
    asm volatile(
        "mma.sync.aligned.m16n8k16.row.col.f16.f16.f16.f16 "
        "{%0,%1}, {%2,%3,%4,%5}, {%6,%7}, {%0,%1};"
        : "+r"(c0), "+r"(c1)
        : "r"(a0), "r"(a1), "r"(a2), "r"(a3), "r"(b0), "r"(b1));
}
__device__ __forceinline__ void mbar_init(uint32_t mbar, uint32_t cnt) {
    asm volatile("mbarrier.init.shared.b64 [%0], %1;" :: "r"(mbar), "r"(cnt) : "memory");
}
__device__ __forceinline__ void mbar_arrive(uint32_t mbar) {
    asm volatile("mbarrier.arrive.shared.b64 _, [%0];" :: "r"(mbar) : "memory");
}
__device__ __forceinline__ void cpasync_arrive(uint32_t mbar) {
    asm volatile("cp.async.mbarrier.arrive.noinc.shared.b64 [%0];" :: "r"(mbar) : "memory");
}
__device__ __forceinline__ void mbar_wait(uint32_t mbar, uint32_t parity) {
    asm volatile(
        "{\n\t.reg .pred P;\n\t"
        "W_%=:\n\t"
        "mbarrier.try_wait.parity.acquire.cta.shared::cta.b64 P, [%0], %1, 0x989680;\n\t"
        "@!P bra W_%=;\n\t}"
        :: "r"(mbar), "r"(parity) : "memory");
}

// ============================================================================
// Single fused kernel: wave-1 CTAs convert (EMA + fp32->fp16) then device-wide
// barrier; all CTAs run the symmetric Gram GEMM + exp + sums; last CTA
// finalizes the loss and resets counters for graph replay.
// ============================================================================
__global__ void __launch_bounds__(128, 3) gemm_exp_kernel(
    const float* __restrict__ protos,
    const float* __restrict__ feats,
    const int*   __restrict__ labels,
    float* __restrict__ out)
{
    const int t   = threadIdx.x;          // 0..127
    const int wid = t >> 5;
    const int lid = t & 31;

    __shared__ int   s_cnt;
    __shared__ int   s_idx[CAP];
    __shared__ float s_red[4];

    // ======================= phase 0: cooperative convert =================
    if (blockIdx.x < WAVE1) {
        const int rows0 = blockIdx.x * ROWS_PER_CTA;
        const int rows1 = min(rows0 + ROWS_PER_CTA, N_CLASS);
        for (int c = rows0; c < rows1; c++) {
            if (t == 0) s_cnt = 0;
            __syncthreads();
            #pragma unroll
            for (int i = t; i < BATCH; i += 128) {
                if (labels[i] == c) {
                    int p = atomicAdd(&s_cnt, 1);
                    if (p < CAP) s_idx[p] = i;
                }
            }
            __syncthreads();

            float4 ra = reinterpret_cast<const float4*>(protos)[(size_t)c * 256 + t];
            float4 rb = reinterpret_cast<const float4*>(protos)[(size_t)c * 256 + 128 + t];

            const int cnt = min(s_cnt, CAP);
            if (cnt > 0) {
                if (t == 0) {  // order matters: insertion-sort the match list
                    for (int a2 = 1; a2 < cnt; a2++) {
                        int v = s_idx[a2], b2 = a2 - 1;
                        while (b2 >= 0 && s_idx[b2] > v) { s_idx[b2 + 1] = s_idx[b2]; b2--; }
                        s_idx[b2 + 1] = v;
                    }
                }
                __syncthreads();
                for (int m = 0; m < cnt; m++) {
                    const int i = s_idx[m];
                    float4 fa = reinterpret_cast<const float4*>(feats)[(size_t)i * 256 + t];
                    float4 fb = reinterpret_cast<const float4*>(feats)[(size_t)i * 256 + 128 + t];
                    ra.x = ra.x * 0.95f + 0.05f * fa.x;
                    ra.y = ra.y * 0.95f + 0.05f * fa.y;
                    ra.z = ra.z * 0.95f + 0.05f * fa.z;
                    ra.w = ra.w * 0.95f + 0.05f * fa.w;
                    rb.x = rb.x * 0.95f + 0.05f * fb.x;
                    rb.y = rb.y * 0.95f + 0.05f * fb.y;
                    rb.z = rb.z * 0.95f + 0.05f * fb.z;
                    rb.w = rb.w * 0.95f + 0.05f * fb.w;
                    float ss = ra.x * ra.x + ra.y * ra.y + ra.z * ra.z + ra.w * ra.w
                             + rb.x * rb.x + rb.y * rb.y + rb.z * rb.z + rb.w * rb.w;
                    #pragma unroll
                    for (int o = 16; o > 0; o >>= 1) ss += __shfl_xor_sync(0xffffffffu, ss, o);
                    if (lid == 0) s_red[wid] = ss;
                    __syncthreads();
                    float tot = s_red[0] + s_red[1] + s_red[2] + s_red[3];
                    float inv = 1.0f / fmaxf(sqrtf(tot), 1e-12f);
                    ra.x *= inv; ra.y *= inv; ra.z *= inv; ra.w *= inv;
                    rb.x *= inv; rb.y *= inv; rb.z *= inv; rb.w *= inv;
                    __syncthreads();
                }
            }
            __half2* dst = reinterpret_cast<__half2*>(g_protos + (size_t)c * FEAT);
            dst[t * 2 + 0]       = __floats2half2_rn(ra.x, ra.y);
            dst[t * 2 + 1]       = __floats2half2_rn(ra.z, ra.w);
            dst[256 + t * 2 + 0] = __floats2half2_rn(rb.x, rb.y);
            dst[256 + t * 2 + 1] = __floats2half2_rn(rb.z, rb.w);
            if (t == 0) g_rowsum[c] = 0.0f;
            __syncthreads();
        }
        // device-wide one-wave barrier
        if (t == 0) {
            __threadfence();
            atomicAdd(&g_ready, 1);
            volatile int* vr = &g_ready;
            while (*vr < WAVE1) { }
            __threadfence();
        }
        __syncthreads();
    }

    // ======================= phase 1: GEMM tile ============================
    // decode linear id -> upper-triangle (ti, tj), row-major
    const int id = blockIdx.x;
    int ti = (int)((2.0f * NTILE + 1.0f
                    - sqrtf((2.0f * NTILE + 1.0f) * (2.0f * NTILE + 1.0f) - 8.0f * id))
                   * 0.5f);
    while ((ti + 1) * NTILE - ((ti + 1) * ti) / 2 <= id) ti++;
    while (ti * NTILE - (ti * (ti - 1)) / 2 > id) ti--;
    const int tj = ti + (id - (ti * NTILE - (ti * (ti - 1)) / 2));

    const bool diag   = (ti == tj);
    const int rowBase = ti * TM;
    const int colBase = tj * TN;

    extern __shared__ __align__(1024) char smem[];
    const uint32_t sb   = smem_u32(smem);
    const uint32_t ctrl = sb + CTRL_OFF;   // wr[0],wr[1] at +0,+8 ; rd[0],rd[1] at +16,+24

    const int wr = wid >> 1;
    const int wc = wid & 1;

    const __half* __restrict__ P = g_protos;

    if (t == 0) {
        #pragma unroll
        for (int s = 0; s < 2; s++) { mbar_init(ctrl + s * 8, 128); mbar_init(ctrl + 16 + s * 8, 128); }
    }
    __syncthreads();

    // ---- async stage loader (16 x 16B per thread), completion via mbarrier ----
    const int kc = t & 7;
    const int r0 = t >> 3;
    const uint32_t dOffA = r0 * 128 + ((kc ^ (r0 & 7)) << 4);
    const __half* pA0 = P + (size_t)(rowBase + r0) * FEAT + kc * 8;
    const __half* pB0 = P + (size_t)(colBase + r0) * FEAT + kc * 8;

    auto load_stage = [&](int kt) {
        const int slot = kt & 1;
        const uint32_t dA = sb + slot * STAGE_BYTES + dOffA;
        const __half* sA = pA0 + kt * TK;
        const __half* sB = pB0 + kt * TK;
        #pragma unroll
        for (int q = 0; q < 8; q++) {
            asm volatile("cp.async.cg.shared.global [%0], [%1], 16;"
                         :: "r"(dA + q * 2048), "l"(sA + (size_t)q * 16 * FEAT));
            asm volatile("cp.async.cg.shared.global [%0], [%1], 16;"
                         :: "r"(dA + A_BYTES + q * 2048), "l"(sB + (size_t)q * 16 * FEAT));
        }
        cpasync_arrive(ctrl + slot * 8);
    };

    load_stage(0);
    load_stage(1);

    uint32_t acc[4][8][2];
    #pragma unroll
    for (int mf = 0; mf < 4; mf++)
        #pragma unroll
        for (int nf = 0; nf < 8; nf++) { acc[mf][nf][0] = 0u; acc[mf][nf][1] = 0u; }

    const int lmod16 = lid & 15;
    const int ldiv16 = lid >> 4;
    const int xsw    = lmod16 & 7;
    uint32_t aOff[4], bOff[4];
    #pragma unroll
    for (int mf = 0; mf < 4; mf++) aOff[mf] = (wr * 64 + mf * 16 + lmod16) * 128;
    #pragma unroll
    for (int np = 0; np < 4; np++) bOff[np] = (wc * 64 + np * 16 + lmod16) * 128;

    uint32_t a[2][4][4];
    uint32_t b[2][8][2];

    auto ldfrag = [&](int buf, int slot, int ks) {
        const uint32_t base = sb + slot * STAGE_BYTES;
        const uint32_t sw = (uint32_t)(((ks * 2 + ldiv16) ^ xsw) << 4);
        #pragma unroll
        for (int mf = 0; mf < 4; mf++)
            ldmatrix_x4(a[buf][mf][0], a[buf][mf][1], a[buf][mf][2], a[buf][mf][3],
                        base + aOff[mf] + sw);
        #pragma unroll
        for (int np = 0; np < 4; np++) {
            uint32_t q0, q1, q2, q3;
            ldmatrix_x4(q0, q1, q2, q3, base + A_BYTES + bOff[np] + sw);
            b[buf][np * 2 + 0][0] = q0; b[buf][np * 2 + 0][1] = q2;
            b[buf][np * 2 + 1][0] = q1; b[buf][np * 2 + 1][1] = q3;
        }
    };

    auto mma_step = [&](int buf) {
        #pragma unroll
        for (int mf = 0; mf < 4; mf++)
            #pragma unroll
            for (int nf = 0; nf < 8; nf++)
                mma_f16acc(acc[mf][nf][0], acc[mf][nf][1],
                           a[buf][mf][0], a[buf][mf][1], a[buf][mf][2], a[buf][mf][3],
                           b[buf][nf][0], b[buf][nf][1]);
    };

    mbar_wait(ctrl + 0, 0);       // stage 0 written
    ldfrag(0, 0, 0);

    #pragma unroll 2
    for (int kt = 0; kt < KTILES; kt++) {
        const int slot = kt & 1;
        ldfrag(1, slot, 1);
        mma_step(0);
        ldfrag(0, slot, 2);
        mma_step(1);
        ldfrag(1, slot, 3);
        mbar_arrive(ctrl + 16 + slot * 8);          // done reading this slot
        mma_step(0);
        if (kt <= KTILES - 3) {
            mbar_wait(ctrl + 16 + slot * 8, (uint32_t)((kt >> 1) & 1));   // all warps done
            load_stage(kt + 2);
        }
        mma_step(1);
        if (kt < KTILES - 1) {
            const int ns = slot ^ 1;
            mbar_wait(ctrl + ns * 8, (uint32_t)(((kt + 1) >> 1) & 1));    // next stage written
            ldfrag(0, ns, 0);
        }
    }

    // ---- epilogue: exp(10*x); direct REDG row sums + (off-diag) col sums ----
    const int g  = lid >> 2;
    const int tg = lid & 3;

    float cs[8][2];
    #pragma unroll
    for (int nf = 0; nf < 8; nf++) { cs[nf][0] = 0.0f; cs[nf][1] = 0.0f; }

    #pragma unroll
    for (int mf = 0; mf < 4; mf++) {
        float rs0 = 0.0f, rs1 = 0.0f;
        const int gr0 = rowBase + wr * 64 + mf * 16 + g;
        const int gr1 = gr0 + 8;
        #pragma unroll
        for (int nf = 0; nf < 8; nf++) {
            float2 lo = __half22float2(*reinterpret_cast<__half2*>(&acc[mf][nf][0]));
            float2 hi = __half22float2(*reinterpret_cast<__half2*>(&acc[mf][nf][1]));
            float e0 = __expf(lo.x * 10.0f);
            float e1 = __expf(lo.y * 10.0f);
            float e2 = __expf(hi.x * 10.0f);
            float e3 = __expf(hi.y * 10.0f);
            if (diag) {
                const int gc0 = colBase + wc * 64 + nf * 8 + 2 * tg;
                const int gc1 = gc0 + 1;
                if (gr0 == gc0) e0 = 0.0f;
                if (gr0 == gc1) e1 = 0.0f;
                if (gr1 == gc0) e2 = 0.0f;
                if (gr1 == gc1) e3 = 0.0f;
            }
            rs0 += e0 + e1;
            rs1 += e2 + e3;
            cs[nf][0] += e0 + e2;
            cs[nf][1] += e1 + e3;
        }
        rs0 += __shfl_xor_sync(0xffffffffu, rs0, 1);
        rs0 += __shfl_xor_sync(0xffffffffu, rs0, 2);
        rs1 += __shfl_xor_sync(0xffffffffu, rs1, 1);
        rs1 += __shfl_xor_sync(0xffffffffu, rs1, 2);
        if (tg == 0) {
            atomicAdd(&g_rowsum[gr0], rs0);
            atomicAdd(&g_rowsum[gr1], rs1);
        }
    }
    if (!diag) {
        #pragma unroll
        for (int nf = 0; nf < 8; nf++) {
            #pragma unroll
            for (int h = 0; h < 2; h++) {
                float v = cs[nf][h];
                v += __shfl_xor_sync(0xffffffffu, v, 4);
                v += __shfl_xor_sync(0xffffffffu, v, 8);
                v += __shfl_xor_sync(0xffffffffu, v, 16);
                if (g == 0)
                    atomicAdd(&g_rowsum[colBase + wc * 64 + nf * 8 + 2 * tg + h], v);
            }
        }
    }

    // ---- last CTA computes the loss and resets counters (graph replay) ----
    __threadfence();
    __syncthreads();
    __shared__ int s_last;
    if (t == 0) s_last = (atomicAdd(&g_done, 1) == NTRI - 1) ? 1 : 0;
    __syncthreads();
    if (s_last) {
        __threadfence();
        float acc2 = 0.0f;
        for (int i = t; i < N_CLASS; i += 128)
            acc2 += logf(g_rowsum[i] * (1.0f / (float)(N_CLASS - 1)));
        #pragma unroll
        for (int o = 16; o > 0; o >>= 1) acc2 += __shfl_xor_sync(0xffffffffu, acc2, o);
        if (lid == 0) s_red[wid] = acc2;
        __syncthreads();
        if (t == 0) {
            out[0] = (s_red[0] + s_red[1] + s_red[2] + s_red[3]) / (float)N_CLASS;
            g_done  = 0;   // reset for next graph replay
            g_ready = 0;
            __threadfence();
        }
    }
}

// ============================================================================
extern "C" void kernel_launch(void* const* d_in, const int* in_sizes, int n_in,
                              void* d_out, int out_size)
{
    const float* features   = nullptr;
    const int*   labels     = nullptr;
    const float* prototypes = nullptr;
    for (int k = 0; k < n_in; k++) {
        if      (in_sizes[k] == BATCH)          labels     = (const int*)d_in[k];
        else if (in_sizes[k] == BATCH * FEAT)   features   = (const float*)d_in[k];
        else if (in_sizes[k] == N_CLASS * FEAT) prototypes = (const float*)d_in[k];
    }
    float* out = (float*)d_out;

    static bool attr_done = false;
    if (!attr_done) {
        cudaFuncSetAttribute(gemm_exp_kernel,
                             cudaFuncAttributeMaxDynamicSharedMemorySize, SMEM_TOTAL);
        attr_done = true;
    }

    gemm_exp_kernel<<<NTRI, 128, SMEM_TOTAL>>>(prototypes, features, labels, out);
    (void)out_size;
}

// round 17
// speedup vs baseline: 1.1377x; 1.1377x over previous
#include <cuda_runtime.h>
#include <cuda_fp16.h>
#include <cstdint>
#include <cstddef>

#define N_CLASS 8192
#define FEAT    1024
#define BATCH   1024

#define TM 128
#define TN 128
#define TK 64
#define KTILES (FEAT / TK)        // 16
#define A_BYTES (TM * 128)        // 16 KB (128 rows x 128B)
#define B_BYTES (TN * 128)        // 16 KB
#define STAGE_BYTES (A_BYTES + B_BYTES)   // 32 KB
#define CTRL_OFF (2 * STAGE_BYTES)        // 64 KB
#define SMEM_TOTAL (CTRL_OFF + 128)

#define NTILE (N_CLASS / TM)                  // 64
#define NTRI  (NTILE * (NTILE + 1) / 2)       // 2080 upper-triangle tiles
#define CAP 32

// ---------------- device scratch (no allocations allowed) ----------------
__device__ __half g_protos[(size_t)N_CLASS * FEAT];  // 16 MB fp16 protos
__device__ float  g_rowsum[N_CLASS];
__device__ int    g_done;

// ---------------- helpers ----------------
__device__ __forceinline__ uint32_t smem_u32(const void* p) {
    uint32_t a;
    asm("{ .reg .u64 t; cvta.to.shared.u64 t, %1; cvt.u32.u64 %0, t; }" : "=r"(a) : "l"(p));
    return a;
}
__device__ __forceinline__ void ldmatrix_x4(uint32_t& r0, uint32_t& r1,
                                            uint32_t& r2, uint32_t& r3, uint32_t addr) {
    asm volatile("ldmatrix.sync.aligned.m8n8.x4.shared.b16 {%0,%1,%2,%3}, [%4];"
                 : "=r"(r0), "=r"(r1), "=r"(r2), "=r"(r3) : "r"(addr));
}
__device__ __forceinline__ void mma_f16acc(uint32_t& c0, uint32_t& c1,
                                           uint32_t a0, uint32_t a1, uint32_t a2, uint32_t a3,
                                           uint32_t b0, uint32_t b1) {
    asm volatile(
        "mma.sync.aligned.m16n8k16.row.col.f16.f16.f16.f16 "
        "{%0,%1}, {%2,%3,%4,%5}, {%6,%7}, {%0,%1};"
        : "+r"(c0), "+r"(c1)
        : "r"(a0), "r"(a1), "r"(a2), "r"(a3), "r"(b0), "r"(b1));
}
__device__ __forceinline__ void mbar_init(uint32_t mbar, uint32_t cnt) {
    asm volatile("mbarrier.init.shared.b64 [%0], %1;" :: "r"(mbar), "r"(cnt) : "memory");
}
__device__ __forceinline__ void mbar_arrive(uint32_t mbar) {
    asm volatile("mbarrier.arrive.shared.b64 _, [%0];" :: "r"(mbar) : "memory");
}
__device__ __forceinline__ void cpasync_arrive(uint32_t mbar) {
    asm volatile("cp.async.mbarrier.arrive.noinc.shared.b64 [%0];" :: "r"(mbar) : "memory");
}
__device__ __forceinline__ void mbar_wait(uint32_t mbar, uint32_t parity) {
    asm volatile(
        "{\n\t.reg .pred P;\n\t"
        "W_%=:\n\t"
        "mbarrier.try_wait.parity.acquire.cta.shared::cta.b64 P, [%0], %1, 0x989680;\n\t"
        "@!P bra W_%=;\n\t}"
        :: "r"(mbar), "r"(parity) : "memory");
}

// ============================================================================
// Kernel 1: fused label-scan + EMA + fp32->fp16 convert. One block per class.
// ============================================================================
__global__ void __launch_bounds__(256) ema_convert_kernel(
    const float* __restrict__ protos,
    const float* __restrict__ feats,
    const int*   __restrict__ labels)
{
    const int c = blockIdx.x;
    const int t = threadIdx.x;

    __shared__ int   s_cnt;
    __shared__ int   s_idx[CAP];
    __shared__ float s_red[8];

    if (t == 0) s_cnt = 0;
    __syncthreads();

    // scan batch labels for this class (labels is 4KB -> L2 resident)
    #pragma unroll
    for (int i = t; i < BATCH; i += 256) {
        if (labels[i] == c) {
            int p = atomicAdd(&s_cnt, 1);
            if (p < CAP) s_idx[p] = i;
        }
    }
    __syncthreads();

    float4 r = reinterpret_cast<const float4*>(protos)[(size_t)c * (FEAT / 4) + t];

    const int cnt = min(s_cnt, CAP);
    if (cnt > 0) {
        if (t == 0) {  // order matters: insertion-sort the (tiny) match list
            for (int a = 1; a < cnt; a++) {
                int v = s_idx[a], b = a - 1;
                while (b >= 0 && s_idx[b] > v) { s_idx[b + 1] = s_idx[b]; b--; }
                s_idx[b + 1] = v;
            }
        }
        __syncthreads();
        for (int m = 0; m < cnt; m++) {
            const int i = s_idx[m];
            float4 f = reinterpret_cast<const float4*>(feats)[(size_t)i * (FEAT / 4) + t];
            r.x = r.x * 0.95f + 0.05f * f.x;
            r.y = r.y * 0.95f + 0.05f * f.y;
            r.z = r.z * 0.95f + 0.05f * f.z;
            r.w = r.w * 0.95f + 0.05f * f.w;
            float ss = r.x * r.x + r.y * r.y + r.z * r.z + r.w * r.w;
            #pragma unroll
            for (int o = 16; o > 0; o >>= 1) ss += __shfl_xor_sync(0xffffffffu, ss, o);
            if ((t & 31) == 0) s_red[t >> 5] = ss;
            __syncthreads();
            float tot = s_red[0] + s_red[1] + s_red[2] + s_red[3]
                      + s_red[4] + s_red[5] + s_red[6] + s_red[7];
            float inv = 1.0f / fmaxf(sqrtf(tot), 1e-12f);
            r.x *= inv; r.y *= inv; r.z *= inv; r.w *= inv;
            __syncthreads();
        }
    }

    __half2* dst = reinterpret_cast<__half2*>(g_protos + (size_t)c * FEAT + (size_t)t * 4);
    dst[0] = __floats2half2_rn(r.x, r.y);
    dst[1] = __floats2half2_rn(r.z, r.w);
    if (t == 0) {
        g_rowsum[c] = 0.0f;
        if (c == 0) g_done = 0;
    }
}

// ============================================================================
// Kernel 2: fused symmetric Gram GEMM (fp16) + exp + row/col sums + finalize.
// 2-slot mbarrier pipeline, 3 CTAs/SM, warp tile 64x64, unroll-2 (R14 proven).
// Epilogue: direct global atomics (no smem staging).
// ============================================================================
__global__ void __launch_bounds__(128, 3) gemm_exp_kernel(float* __restrict__ out)
{
    // decode linear id -> upper-triangle (ti, tj), row-major
    const int id = blockIdx.x;
    int ti = (int)((2.0f * NTILE + 1.0f
                    - sqrtf((2.0f * NTILE + 1.0f) * (2.0f * NTILE + 1.0f) - 8.0f * id))
                   * 0.5f);
    while ((ti + 1) * NTILE - ((ti + 1) * ti) / 2 <= id) ti++;
    while (ti * NTILE - (ti * (ti - 1)) / 2 > id) ti--;
    const int tj = ti + (id - (ti * NTILE - (ti * (ti - 1)) / 2));

    const bool diag   = (ti == tj);
    const int rowBase = ti * TM;
    const int colBase = tj * TN;

    extern __shared__ __align__(1024) char smem[];
    const uint32_t sb   = smem_u32(smem);
    const uint32_t ctrl = sb + CTRL_OFF;   // wr[0],wr[1] at +0,+8 ; rd[0],rd[1] at +16,+24

    const int t   = threadIdx.x;          // 0..127
    const int wid = t >> 5;
    const int lid = t & 31;
    const int wr  = wid >> 1;
    const int wc  = wid & 1;

    const __half* __restrict__ P = g_protos;

    if (t == 0) {
        #pragma unroll
        for (int s = 0; s < 2; s++) { mbar_init(ctrl + s * 8, 128); mbar_init(ctrl + 16 + s * 8, 128); }
    }
    __syncthreads();

    // ---- async stage loader (16 x 16B per thread), completion via mbarrier ----
    const int kc = t & 7;
    const int r0 = t >> 3;
    const uint32_t dOffA = r0 * 128 + ((kc ^ (r0 & 7)) << 4);
    const __half* pA0 = P + (size_t)(rowBase + r0) * FEAT + kc * 8;
    const __half* pB0 = P + (size_t)(colBase + r0) * FEAT + kc * 8;

    auto load_stage = [&](int kt) {
        const int slot = kt & 1;
        const uint32_t dA = sb + slot * STAGE_BYTES + dOffA;
        const __half* sA = pA0 + kt * TK;
        const __half* sB = pB0 + kt * TK;
        #pragma unroll
        for (int q = 0; q < 8; q++) {
            asm volatile("cp.async.cg.shared.global [%0], [%1], 16;"
                         :: "r"(dA + q * 2048), "l"(sA + (size_t)q * 16 * FEAT));
            asm volatile("cp.async.cg.shared.global [%0], [%1], 16;"
                         :: "r"(dA + A_BYTES + q * 2048), "l"(sB + (size_t)q * 16 * FEAT));
        }
        cpasync_arrive(ctrl + slot * 8);
    };

    load_stage(0);
    load_stage(1);

    uint32_t acc[4][8][2];
    #pragma unroll
    for (int mf = 0; mf < 4; mf++)
        #pragma unroll
        for (int nf = 0; nf < 8; nf++) { acc[mf][nf][0] = 0u; acc[mf][nf][1] = 0u; }

    const int lmod16 = lid & 15;
    const int ldiv16 = lid >> 4;
    const int xsw    = lmod16 & 7;
    uint32_t aOff[4], bOff[4];
    #pragma unroll
    for (int mf = 0; mf < 4; mf++) aOff[mf] = (wr * 64 + mf * 16 + lmod16) * 128;
    #pragma unroll
    for (int np = 0; np < 4; np++) bOff[np] = (wc * 64 + np * 16 + lmod16) * 128;

    uint32_t a[2][4][4];
    uint32_t b[2][8][2];

    auto ldfrag = [&](int buf, int slot, int ks) {
        const uint32_t base = sb + slot * STAGE_BYTES;
        const uint32_t sw = (uint32_t)(((ks * 2 + ldiv16) ^ xsw) << 4);
        #pragma unroll
        for (int mf = 0; mf < 4; mf++)
            ldmatrix_x4(a[buf][mf][0], a[buf][mf][1], a[buf][mf][2], a[buf][mf][3],
                        base + aOff[mf] + sw);
        #pragma unroll
        for (int np = 0; np < 4; np++) {
            uint32_t q0, q1, q2, q3;
            ldmatrix_x4(q0, q1, q2, q3, base + A_BYTES + bOff[np] + sw);
            b[buf][np * 2 + 0][0] = q0; b[buf][np * 2 + 0][1] = q2;
            b[buf][np * 2 + 1][0] = q1; b[buf][np * 2 + 1][1] = q3;
        }
    };

    auto mma_step = [&](int buf) {
        #pragma unroll
        for (int mf = 0; mf < 4; mf++)
            #pragma unroll
            for (int nf = 0; nf < 8; nf++)
                mma_f16acc(acc[mf][nf][0], acc[mf][nf][1],
                           a[buf][mf][0], a[buf][mf][1], a[buf][mf][2], a[buf][mf][3],
                           b[buf][nf][0], b[buf][nf][1]);
    };

    mbar_wait(ctrl + 0, 0);       // stage 0 written
    ldfrag(0, 0, 0);

    #pragma unroll 2
    for (int kt = 0; kt < KTILES; kt++) {
        const int slot = kt & 1;
        ldfrag(1, slot, 1);
        mma_step(0);
        ldfrag(0, slot, 2);
        mma_step(1);
        ldfrag(1, slot, 3);
        mbar_arrive(ctrl + 16 + slot * 8);          // done reading this slot
        mma_step(0);
        if (kt <= KTILES - 3) {
            mbar_wait(ctrl + 16 + slot * 8, (uint32_t)((kt >> 1) & 1));   // all warps done
            load_stage(kt + 2);
        }
        mma_step(1);
        if (kt < KTILES - 1) {
            const int ns = slot ^ 1;
            mbar_wait(ctrl + ns * 8, (uint32_t)(((kt + 1) >> 1) & 1));    // next stage written
            ldfrag(0, ns, 0);
        }
    }

    // ---- epilogue: exp(10*x); direct global atomics (no smem staging) ----
    const int g  = lid >> 2;
    const int tg = lid & 3;

    float cs[8][2];
    #pragma unroll
    for (int nf = 0; nf < 8; nf++) { cs[nf][0] = 0.0f; cs[nf][1] = 0.0f; }

    #pragma unroll
    for (int mf = 0; mf < 4; mf++) {
        float rs0 = 0.0f, rs1 = 0.0f;
        const int gr0 = rowBase + wr * 64 + mf * 16 + g;
        const int gr1 = gr0 + 8;
        #pragma unroll
        for (int nf = 0; nf < 8; nf++) {
            float2 lo = __half22float2(*reinterpret_cast<__half2*>(&acc[mf][nf][0]));
            float2 hi = __half22float2(*reinterpret_cast<__half2*>(&acc[mf][nf][1]));
            float e0 = __expf(lo.x * 10.0f);
            float e1 = __expf(lo.y * 10.0f);
            float e2 = __expf(hi.x * 10.0f);
            float e3 = __expf(hi.y * 10.0f);
            if (diag) {
                const int gc0 = colBase + wc * 64 + nf * 8 + 2 * tg;
                const int gc1 = gc0 + 1;
                if (gr0 == gc0) e0 = 0.0f;
                if (gr0 == gc1) e1 = 0.0f;
                if (gr1 == gc0) e2 = 0.0f;
                if (gr1 == gc1) e3 = 0.0f;
            }
            rs0 += e0 + e1;
            rs1 += e2 + e3;
            cs[nf][0] += e0 + e2;
            cs[nf][1] += e1 + e3;
        }
        rs0 += __shfl_xor_sync(0xffffffffu, rs0, 1);
        rs0 += __shfl_xor_sync(0xffffffffu, rs0, 2);
        rs1 += __shfl_xor_sync(0xffffffffu, rs1, 1);
        rs1 += __shfl_xor_sync(0xffffffffu, rs1, 2);
        if (tg == 0) {
            atomicAdd(&g_rowsum[gr0], rs0);
            atomicAdd(&g_rowsum[gr1], rs1);
        }
    }
    if (!diag) {
        #pragma unroll
        for (int nf = 0; nf < 8; nf++) {
            #pragma unroll
            for (int h = 0; h < 2; h++) {
                float v = cs[nf][h];
                v += __shfl_xor_sync(0xffffffffu, v, 4);
                v += __shfl_xor_sync(0xffffffffu, v, 8);
                v += __shfl_xor_sync(0xffffffffu, v, 16);
                if (g == 0)
                    atomicAdd(&g_rowsum[colBase + wc * 64 + nf * 8 + 2 * tg + h], v);
            }
        }
    }

    // ---- last CTA computes the loss ----
    __threadfence();
    __syncthreads();
    __shared__ int s_last;
    __shared__ float s_fin[4];
    if (t == 0) s_last = (atomicAdd(&g_done, 1) == NTRI - 1) ? 1 : 0;
    __syncthreads();
    if (s_last) {
        __threadfence();
        float acc2 = 0.0f;
        for (int i = t; i < N_CLASS; i += 128)
            acc2 += logf(g_rowsum[i] * (1.0f / (float)(N_CLASS - 1)));
        #pragma unroll
        for (int o = 16; o > 0; o >>= 1) acc2 += __shfl_xor_sync(0xffffffffu, acc2, o);
        if (lid == 0) s_fin[wid] = acc2;
        __syncthreads();
        if (t == 0)
            out[0] = (s_fin[0] + s_fin[1] + s_fin[2] + s_fin[3]) / (float)N_CLASS;
    }
}

// ============================================================================
extern "C" void kernel_launch(void* const* d_in, const int* in_sizes, int n_in,
                              void* d_out, int out_size)
{
    const float* features   = nullptr;
    const int*   labels     = nullptr;
    const float* prototypes = nullptr;
    for (int k = 0; k < n_in; k++) {
        if      (in_sizes[k] == BATCH)          labels     = (const int*)d_in[k];
        else if (in_sizes[k] == BATCH * FEAT)   features   = (const float*)d_in[k];
        else if (in_sizes[k] == N_CLASS * FEAT) prototypes = (const float*)d_in[k];
    }
    float* out = (float*)d_out;

    static bool attr_done = false;
    if (!attr_done) {
        cudaFuncSetAttribute(gemm_exp_kernel,
                             cudaFuncAttributeMaxDynamicSharedMemorySize, SMEM_TOTAL);
        attr_done = true;
    }

    ema_convert_kernel<<<N_CLASS, 256>>>(prototypes, features, labels);
    gemm_exp_kernel<<<NTRI, 128, SMEM_TOTAL>>>(out);
    (void)out_size;
}